// round 10
// baseline (speedup 1.0000x reference)
#include <cuda_runtime.h>
#include <cuda_fp16.h>

#define PP 4
#define NN 65536
#define DD 128
#define OO 128
#define EE 500000
#define MM 32768
#define TOTAL_ROWS 655360   // 4*N + 12*M
#define NEDGES (16 * EE)    // 8,000,000
#define NTILES 640          // scan tiles of 1024

#define BM 128
#define BK 32
#define AS_STRIDE 36
#define BS_STRIDE 136

#define SCAT_BLKS  2048
#define F2_GRID    6144       // 3 * 2048, pattern [g,g,s]

// ---------------- scratch ----------------
__device__ __half g_FN[(size_t)PP * NN * OO];        // feats @ W_neigh, fp16 (67 MB)
__device__ __half g_SelfM[(size_t)PP * MM * OO];     // (feats@W_self + b) rows [0,M), fp16 (33 MB)
__device__ int   g_cnt[TOTAL_ROWS];
__device__ int   g_off[TOTAL_ROWS];
__device__ int   g_cur[TOTAL_ROWS];
__device__ unsigned long long g_state[NTILES];       // decoupled-lookback tile state
__device__ unsigned short g_sorted_src[NEDGES];      // src ids (<65536) sorted by dst row (16 MB)

__constant__ int c_blkoff[17] = {
    0,      65536,  98304,  131072,
    163840, 196608, 262144, 294912,
    327680, 360448, 393216, 458752,
    491520, 524288, 557056, 589824, 655360};

__device__ __forceinline__ unsigned f2tf32(float v) {
    unsigned r;
    asm("cvt.rna.tf32.f32 %0, %1;" : "=r"(r) : "f"(v));
    return r;
}

// ---------------- GEMM tile worker (non-pipelined tf32 MMA) ----------------
__device__ __forceinline__ void gemm_tile(
    int tileId,
    const float* __restrict__ feats, const float* __restrict__ Ws,
    const float* __restrict__ Wn, const float* __restrict__ bias,
    float* __restrict__ out,
    unsigned (*As)[AS_STRIDE], unsigned (*Bs)[BS_STRIDE])
{
    const int x  = tileId & 511;
    const int yz = tileId >> 9;
    const bool isSelf = (yz & 1) == 0;
    const int s  = yz >> 1;
    const int row0 = x * BM;

    const float* A = feats + (size_t)s * NN * DD;
    const float* B = (isSelf ? Ws : Wn) + (size_t)s * DD * OO;

    const int t    = threadIdx.x;
    const int lane = t & 31;
    const int wid  = t >> 5;
    const int wm   = wid >> 1;
    const int wn   = wid & 1;

    float C[2][8][4];
#pragma unroll
    for (int mf = 0; mf < 2; mf++)
#pragma unroll
        for (int j = 0; j < 8; j++)
#pragma unroll
            for (int q = 0; q < 4; q++) C[mf][j][q] = 0.0f;

    for (int kt = 0; kt < DD; kt += BK) {
#pragma unroll
        for (int q = 0; q < 4; q++) {
            int i  = t + 256 * q;
            int r  = i >> 3;
            int k0 = (i & 7) * 4;
            float4 v = *(const float4*)(A + (size_t)(row0 + r) * DD + kt + k0);
            *(uint4*)&As[r][k0] = make_uint4(f2tf32(v.x), f2tf32(v.y),
                                             f2tf32(v.z), f2tf32(v.w));
        }
#pragma unroll
        for (int q = 0; q < 4; q++) {
            int i  = t + 256 * q;
            int k  = i >> 5;
            int n0 = (i & 31) * 4;
            float4 v = *(const float4*)(B + (size_t)(kt + k) * OO + n0);
            *(uint4*)&Bs[k][n0] = make_uint4(f2tf32(v.x), f2tf32(v.y),
                                             f2tf32(v.z), f2tf32(v.w));
        }
        __syncthreads();

#pragma unroll
        for (int kk = 0; kk < BK; kk += 8) {
            unsigned a[2][4];
#pragma unroll
            for (int mf = 0; mf < 2; mf++) {
                int r = wm * 32 + mf * 16 + (lane >> 2);
                int kc = kk + (lane & 3);
                a[mf][0] = As[r][kc];
                a[mf][1] = As[r + 8][kc];
                a[mf][2] = As[r][kc + 4];
                a[mf][3] = As[r + 8][kc + 4];
            }
#pragma unroll
            for (int j = 0; j < 8; j++) {
                int n = wn * 64 + j * 8 + (lane >> 2);
                unsigned b0 = Bs[kk + (lane & 3)][n];
                unsigned b1 = Bs[kk + (lane & 3) + 4][n];
#pragma unroll
                for (int mf = 0; mf < 2; mf++) {
                    asm("mma.sync.aligned.m16n8k8.row.col.f32.tf32.tf32.f32 "
                        "{%0,%1,%2,%3}, {%4,%5,%6,%7}, {%8,%9}, {%0,%1,%2,%3};"
                        : "+f"(C[mf][j][0]), "+f"(C[mf][j][1]),
                          "+f"(C[mf][j][2]), "+f"(C[mf][j][3])
                        : "r"(a[mf][0]), "r"(a[mf][1]),
                          "r"(a[mf][2]), "r"(a[mf][3]),
                          "r"(b0), "r"(b1));
                }
            }
        }
        __syncthreads();
    }

    const int col0 = wn * 64;
    if (isSelf) {
#pragma unroll
        for (int mf = 0; mf < 2; mf++) {
            int r0 = row0 + wm * 32 + mf * 16 + (lane >> 2);
#pragma unroll
            for (int j = 0; j < 8; j++) {
                int c = col0 + j * 8 + (lane & 3) * 2;
                float b0v = __ldg(bias + s * OO + c);
                float b1v = __ldg(bias + s * OO + c + 1);
                float2 v0 = make_float2(C[mf][j][0] + b0v, C[mf][j][1] + b1v);
                float2 v1 = make_float2(C[mf][j][2] + b0v, C[mf][j][3] + b1v);
                *(float2*)(out + ((size_t)s * NN + r0) * OO + c)     = v0;
                *(float2*)(out + ((size_t)s * NN + r0 + 8) * OO + c) = v1;
                if (r0 < MM) {
                    *(__half2*)(g_SelfM + ((size_t)s * MM + r0) * OO + c)
                        = __floats2half2_rn(v0.x, v0.y);
                    *(__half2*)(g_SelfM + ((size_t)s * MM + r0 + 8) * OO + c)
                        = __floats2half2_rn(v1.x, v1.y);
                }
            }
        }
    } else {
#pragma unroll
        for (int mf = 0; mf < 2; mf++) {
            int r0 = row0 + wm * 32 + mf * 16 + (lane >> 2);
#pragma unroll
            for (int j = 0; j < 8; j++) {
                int c = col0 + j * 8 + (lane & 3) * 2;
                *(__half2*)(g_FN + ((size_t)s * NN + r0) * OO + c)
                    = __floats2half2_rn(C[mf][j][0], C[mf][j][1]);
                *(__half2*)(g_FN + ((size_t)s * NN + r0 + 8) * OO + c)
                    = __floats2half2_rn(C[mf][j][2], C[mf][j][3]);
            }
        }
    }
}

// ---------------- scatter worker (grid-stride over edges) ----------------
__device__ __forceinline__ void scatter_work(
    int chunk, const int* __restrict__ e_src, const int* __restrict__ e_dst)
{
    const int stride = SCAT_BLKS * 256;
    for (int e = chunk * 256 + threadIdx.x; e < NEDGES; e += stride) {
        int blk = e / EE;
        int row = c_blkoff[blk] + __ldg(e_dst + e);
        int pos = atomicAdd(&g_cur[row], 1);
        g_sorted_src[pos] = (unsigned short)__ldg(e_src + e);
    }
}

// ---------------- F2: fused GEMM + scatter (dispatch-interleaved 2:1) ----------------
__global__ __launch_bounds__(256, 2) void gemm_scatter(
    const float* __restrict__ feats, const float* __restrict__ Ws,
    const float* __restrict__ Wn, const float* __restrict__ bias,
    float* __restrict__ out,
    const int* __restrict__ e_src, const int* __restrict__ e_dst)
{
    __shared__ unsigned As[BM][AS_STRIDE];
    __shared__ unsigned Bs[BK][BS_STRIDE];

    const int bx = blockIdx.x;
    const int p  = bx % 3;
    const int g3 = bx / 3;
    if (p < 2) {
        gemm_tile(g3 * 2 + p, feats, Ws, Wn, bias, out, As, Bs);
    } else {
        scatter_work(g3, e_src, e_dst);
    }
}

// ---------------- histogram (int4 vectorized) ----------------
__global__ __launch_bounds__(256) void hist_kernel(const int* __restrict__ e_dst)
{
    int i = blockIdx.x * 256 + threadIdx.x;
    if (i >= NEDGES / 4) return;
    int4 d4 = __ldg((const int4*)e_dst + i);
    int bo = c_blkoff[(i * 4) / EE];      // EE % 4 == 0 -> all 4 in same block
    atomicAdd(&g_cnt[bo + d4.x], 1);
    atomicAdd(&g_cnt[bo + d4.y], 1);
    atomicAdd(&g_cnt[bo + d4.z], 1);
    atomicAdd(&g_cnt[bo + d4.w], 1);
}

// ---------------- single-pass decoupled-lookback scan ----------------
// grid NTILES x 256 threads, 4 items/thread (tile = 1024 elements)
__global__ __launch_bounds__(256) void scan_kernel()
{
    __shared__ int sm[256];
    __shared__ int s_prefix;

    const int tile  = blockIdx.x;
    const int tid   = threadIdx.x;
    const int tbase = tile * 1024;

    int4 v = *(const int4*)(g_cnt + tbase + tid * 4);
    int tsum = v.x + v.y + v.z + v.w;

    sm[tid] = tsum;
    __syncthreads();
    for (int ofs = 1; ofs < 256; ofs <<= 1) {
        int t = (tid >= ofs) ? sm[tid - ofs] : 0;
        __syncthreads();
        sm[tid] += t;
        __syncthreads();
    }
    int excl  = sm[tid] - tsum;
    int total = sm[255];

    if (tid == 0) {
        if (tile == 0) {
            atomicExch(&g_state[0], (2ULL << 32) | (unsigned)total);
            s_prefix = 0;
        } else {
            atomicExch(&g_state[tile], (1ULL << 32) | (unsigned)total);
            long long run = 0;
            int t = tile - 1;
            while (true) {
                unsigned long long st;
                do { st = atomicAdd(&g_state[t], 0ULL); } while ((st >> 32) == 0);
                run += (unsigned)st;
                if ((st >> 32) == 2) break;
                t--;
            }
            atomicExch(&g_state[tile], (2ULL << 32) | (unsigned)(run + total));
            s_prefix = (int)run;
        }
    }
    __syncthreads();

    int base = s_prefix + excl;
    int4 o;
    o.x = base;
    o.y = o.x + v.x;
    o.z = o.y + v.y;
    o.w = o.z + v.z;
    *(int4*)(g_off + tbase + tid * 4) = o;
    *(int4*)(g_cur + tbase + tid * 4) = o;
}

// ---------------- Phase B+C fused: warp/row, 16B lanes, fp16 accumulation ----------------
__global__ __launch_bounds__(256) void agg_combine(
    float* __restrict__ out, const int* __restrict__ merge)
{
    const int lane = threadIdx.x & 31;
    const int half = lane >> 4;          // 0/1: which edge of the pair
    const int sub  = lane & 15;          // uint4 index within 256B row
    const int r = blockIdx.x * 8 + (threadIdx.x >> 5);

    int blk = 0;
#pragma unroll
    for (int k = 1; k < 16; k++)
        if (r >= c_blkoff[k]) blk = k;
    const int s = blk >> 2, d = blk & 3;
    const int lrow = r - c_blkoff[blk];

    const int base = g_off[r];
    const int deg  = g_cnt[r];
    const uint4* FNs = (const uint4*)(g_FN + (size_t)s * NN * OO);   // 16 uint4 per row

    __half2 hz; *(unsigned*)&hz = 0u;
    __half2 hacc0 = hz, hacc1 = hz, hacc2 = hz, hacc3 = hz;

    for (int i0 = 0; i0 < deg; i0 += 32) {
        int mi = i0 + lane;
        int msrc = (mi < deg) ? (int)g_sorted_src[base + mi] : 0;
        int cnt = min(32, deg - i0);
        for (int j = 0; j < cnt; j += 2) {
            int idx = j + half;
            int src = __shfl_sync(0xffffffffu, msrc, idx);
            if (idx < cnt) {
                uint4 raw = __ldg(FNs + (size_t)src * 16 + sub);
                hacc0 = __hadd2(hacc0, *(__half2*)&raw.x);
                hacc1 = __hadd2(hacc1, *(__half2*)&raw.y);
                hacc2 = __hadd2(hacc2, *(__half2*)&raw.z);
                hacc3 = __hadd2(hacc3, *(__half2*)&raw.w);
            }
        }
    }

    float acc[8];
    {
        float2 f0 = __half22float2(hacc0);
        float2 f1 = __half22float2(hacc1);
        float2 f2 = __half22float2(hacc2);
        float2 f3 = __half22float2(hacc3);
        acc[0] = f0.x; acc[1] = f0.y; acc[2] = f1.x; acc[3] = f1.y;
        acc[4] = f2.x; acc[5] = f2.y; acc[6] = f3.x; acc[7] = f3.y;
    }
#pragma unroll
    for (int q = 0; q < 8; q++)
        acc[q] += __shfl_xor_sync(0xffffffffu, acc[q], 16);

    const float invd = (deg > 0) ? (1.0f / (float)deg) : 0.0f;
    const int c0 = sub * 8 + half * 4;   // 4 output cols per lane
    const int ai = half * 4;

    if (s == d) {
        if (deg == 0) return;
        float* op = out + ((size_t)d * NN + lrow) * OO + c0;
        asm volatile("red.global.add.v4.f32 [%0], {%1,%2,%3,%4};"
                     :: "l"(op),
                        "f"(acc[ai] * invd), "f"(acc[ai + 1] * invd),
                        "f"(acc[ai + 2] * invd), "f"(acc[ai + 3] * invd) : "memory");
    } else {
        uint2 smr = *(const uint2*)(g_SelfM + ((size_t)s * MM + lrow) * OO + c0);
        float2 s0 = __half22float2(*(__half2*)&smr.x);
        float2 s1 = __half22float2(*(__half2*)&smr.y);
        float4 v;
        v.x = fmaf(acc[ai],     invd, s0.x);
        v.y = fmaf(acc[ai + 1], invd, s0.y);
        v.z = fmaf(acc[ai + 2], invd, s1.x);
        v.w = fmaf(acc[ai + 3], invd, s1.y);
        int tgt = __ldg(merge + (size_t)blk * MM + lrow);
        float* op = out + ((size_t)d * NN + tgt) * OO + c0;
        asm volatile("red.global.add.v4.f32 [%0], {%1,%2,%3,%4};"
                     :: "l"(op), "f"(v.x), "f"(v.y), "f"(v.z), "f"(v.w) : "memory");
    }
}

// ---------------- launch ----------------
extern "C" void kernel_launch(void* const* d_in, const int* in_sizes, int n_in,
                              void* d_out, int out_size)
{
    const float* feats  = (const float*)d_in[0];   // [P,N,D]
    const float* Wself  = (const float*)d_in[1];   // [P,D,O]
    const float* Wneigh = (const float*)d_in[2];   // [P,D,O]
    const float* bias   = (const float*)d_in[3];   // [P,O]
    const int*   e_src  = (const int*)d_in[4];     // [P,P,E]
    const int*   e_dst  = (const int*)d_in[5];     // [P,P,E]
    const int*   merge  = (const int*)d_in[6];     // [P,P,M]
    float* out = (float*)d_out;                    // [P,N,O]

    void* cntPtr = nullptr; cudaGetSymbolAddress(&cntPtr, g_cnt);
    void* stPtr  = nullptr; cudaGetSymbolAddress(&stPtr,  g_state);
    cudaMemsetAsync(cntPtr, 0, sizeof(int) * (size_t)TOTAL_ROWS, 0);
    cudaMemsetAsync(stPtr,  0, sizeof(unsigned long long) * NTILES, 0);

    hist_kernel<<<(NEDGES / 4 + 255) / 256, 256>>>(e_dst);
    scan_kernel<<<NTILES, 256>>>();

    gemm_scatter<<<F2_GRID, 256>>>(feats, Wself, Wneigh, bias, out, e_src, e_dst);

    agg_combine<<<TOTAL_ROWS / 8, 256>>>(out, merge);
}

// round 11
// speedup vs baseline: 1.1313x; 1.1313x over previous
#include <cuda_runtime.h>
#include <cuda_fp16.h>

#define PP 4
#define NN 65536
#define DD 128
#define OO 128
#define EE 500000
#define MM 32768
#define TOTAL_ROWS 655360   // 4*N + 12*M
#define NEDGES (16 * EE)    // 8,000,000
#define NTILES 640          // scan tiles of 1024

#define BM 128
#define BK 32
#define AS_STRIDE 36
#define BS_STRIDE 136

#define SCAT_BLKS  2048
#define F2_GRID    6144       // 3 * 2048, pattern [g,g,s]

// ---------------- scratch ----------------
__device__ __half g_FN[(size_t)PP * NN * OO];        // feats @ W_neigh, fp16 (67 MB)
__device__ __half g_SelfM[(size_t)PP * MM * OO];     // (feats@W_self + b) rows [0,M), fp16 (33 MB)
__device__ int   g_cnt[TOTAL_ROWS];
__device__ int   g_off[TOTAL_ROWS];
__device__ int   g_cur[TOTAL_ROWS];
__device__ unsigned long long g_state[NTILES];       // decoupled-lookback tile state
__device__ unsigned short g_sorted_src[NEDGES];      // src ids (<65536) sorted by dst row (16 MB)

__constant__ int c_blkoff[17] = {
    0,      65536,  98304,  131072,
    163840, 196608, 262144, 294912,
    327680, 360448, 393216, 458752,
    491520, 524288, 557056, 589824, 655360};

__device__ __forceinline__ unsigned f2tf32(float v) {
    unsigned r;
    asm("cvt.rna.tf32.f32 %0, %1;" : "=r"(r) : "f"(v));
    return r;
}

// ---------------- GEMM tile worker (non-pipelined tf32 MMA) ----------------
__device__ __forceinline__ void gemm_tile(
    int tileId,
    const float* __restrict__ feats, const float* __restrict__ Ws,
    const float* __restrict__ Wn, const float* __restrict__ bias,
    float* __restrict__ out,
    unsigned (*As)[AS_STRIDE], unsigned (*Bs)[BS_STRIDE])
{
    const int x  = tileId & 511;
    const int yz = tileId >> 9;
    const bool isSelf = (yz & 1) == 0;
    const int s  = yz >> 1;
    const int row0 = x * BM;

    const float* A = feats + (size_t)s * NN * DD;
    const float* B = (isSelf ? Ws : Wn) + (size_t)s * DD * OO;

    const int t    = threadIdx.x;
    const int lane = t & 31;
    const int wid  = t >> 5;
    const int wm   = wid >> 1;
    const int wn   = wid & 1;

    float C[2][8][4];
#pragma unroll
    for (int mf = 0; mf < 2; mf++)
#pragma unroll
        for (int j = 0; j < 8; j++)
#pragma unroll
            for (int q = 0; q < 4; q++) C[mf][j][q] = 0.0f;

    for (int kt = 0; kt < DD; kt += BK) {
#pragma unroll
        for (int q = 0; q < 4; q++) {
            int i  = t + 256 * q;
            int r  = i >> 3;
            int k0 = (i & 7) * 4;
            float4 v = *(const float4*)(A + (size_t)(row0 + r) * DD + kt + k0);
            *(uint4*)&As[r][k0] = make_uint4(f2tf32(v.x), f2tf32(v.y),
                                             f2tf32(v.z), f2tf32(v.w));
        }
#pragma unroll
        for (int q = 0; q < 4; q++) {
            int i  = t + 256 * q;
            int k  = i >> 5;
            int n0 = (i & 31) * 4;
            float4 v = *(const float4*)(B + (size_t)(kt + k) * OO + n0);
            *(uint4*)&Bs[k][n0] = make_uint4(f2tf32(v.x), f2tf32(v.y),
                                             f2tf32(v.z), f2tf32(v.w));
        }
        __syncthreads();

#pragma unroll
        for (int kk = 0; kk < BK; kk += 8) {
            unsigned a[2][4];
#pragma unroll
            for (int mf = 0; mf < 2; mf++) {
                int r = wm * 32 + mf * 16 + (lane >> 2);
                int kc = kk + (lane & 3);
                a[mf][0] = As[r][kc];
                a[mf][1] = As[r + 8][kc];
                a[mf][2] = As[r][kc + 4];
                a[mf][3] = As[r + 8][kc + 4];
            }
#pragma unroll
            for (int j = 0; j < 8; j++) {
                int n = wn * 64 + j * 8 + (lane >> 2);
                unsigned b0 = Bs[kk + (lane & 3)][n];
                unsigned b1 = Bs[kk + (lane & 3) + 4][n];
#pragma unroll
                for (int mf = 0; mf < 2; mf++) {
                    asm("mma.sync.aligned.m16n8k8.row.col.f32.tf32.tf32.f32 "
                        "{%0,%1,%2,%3}, {%4,%5,%6,%7}, {%8,%9}, {%0,%1,%2,%3};"
                        : "+f"(C[mf][j][0]), "+f"(C[mf][j][1]),
                          "+f"(C[mf][j][2]), "+f"(C[mf][j][3])
                        : "r"(a[mf][0]), "r"(a[mf][1]),
                          "r"(a[mf][2]), "r"(a[mf][3]),
                          "r"(b0), "r"(b1));
                }
            }
        }
        __syncthreads();
    }

    const int col0 = wn * 64;
    if (isSelf) {
#pragma unroll
        for (int mf = 0; mf < 2; mf++) {
            int r0 = row0 + wm * 32 + mf * 16 + (lane >> 2);
#pragma unroll
            for (int j = 0; j < 8; j++) {
                int c = col0 + j * 8 + (lane & 3) * 2;
                float b0v = __ldg(bias + s * OO + c);
                float b1v = __ldg(bias + s * OO + c + 1);
                float2 v0 = make_float2(C[mf][j][0] + b0v, C[mf][j][1] + b1v);
                float2 v1 = make_float2(C[mf][j][2] + b0v, C[mf][j][3] + b1v);
                *(float2*)(out + ((size_t)s * NN + r0) * OO + c)     = v0;
                *(float2*)(out + ((size_t)s * NN + r0 + 8) * OO + c) = v1;
                if (r0 < MM) {
                    *(__half2*)(g_SelfM + ((size_t)s * MM + r0) * OO + c)
                        = __floats2half2_rn(v0.x, v0.y);
                    *(__half2*)(g_SelfM + ((size_t)s * MM + r0 + 8) * OO + c)
                        = __floats2half2_rn(v1.x, v1.y);
                }
            }
        }
    } else {
#pragma unroll
        for (int mf = 0; mf < 2; mf++) {
            int r0 = row0 + wm * 32 + mf * 16 + (lane >> 2);
#pragma unroll
            for (int j = 0; j < 8; j++) {
                int c = col0 + j * 8 + (lane & 3) * 2;
                *(__half2*)(g_FN + ((size_t)s * NN + r0) * OO + c)
                    = __floats2half2_rn(C[mf][j][0], C[mf][j][1]);
                *(__half2*)(g_FN + ((size_t)s * NN + r0 + 8) * OO + c)
                    = __floats2half2_rn(C[mf][j][2], C[mf][j][3]);
            }
        }
    }
}

// ---------------- scatter worker (grid-stride over edges) ----------------
__device__ __forceinline__ void scatter_work(
    int chunk, const int* __restrict__ e_src, const int* __restrict__ e_dst)
{
    const int stride = SCAT_BLKS * 256;
    for (int e = chunk * 256 + threadIdx.x; e < NEDGES; e += stride) {
        int blk = e / EE;
        int row = c_blkoff[blk] + __ldg(e_dst + e);
        int pos = atomicAdd(&g_cur[row], 1);
        g_sorted_src[pos] = (unsigned short)__ldg(e_src + e);
    }
}

// ---------------- F2: fused GEMM + scatter (dispatch-interleaved 2:1) ----------------
__global__ __launch_bounds__(256, 2) void gemm_scatter(
    const float* __restrict__ feats, const float* __restrict__ Ws,
    const float* __restrict__ Wn, const float* __restrict__ bias,
    float* __restrict__ out,
    const int* __restrict__ e_src, const int* __restrict__ e_dst)
{
    __shared__ unsigned As[BM][AS_STRIDE];
    __shared__ unsigned Bs[BK][BS_STRIDE];

    const int bx = blockIdx.x;
    const int p  = bx % 3;
    const int g3 = bx / 3;
    if (p < 2) {
        gemm_tile(g3 * 2 + p, feats, Ws, Wn, bias, out, As, Bs);
    } else {
        scatter_work(g3, e_src, e_dst);
    }
}

// ---------------- histogram (int4 vectorized) ----------------
__global__ __launch_bounds__(256) void hist_kernel(const int* __restrict__ e_dst)
{
    int i = blockIdx.x * 256 + threadIdx.x;
    if (i >= NEDGES / 4) return;
    int4 d4 = __ldg((const int4*)e_dst + i);
    int bo = c_blkoff[(i * 4) / EE];      // EE % 4 == 0 -> all 4 in same block
    atomicAdd(&g_cnt[bo + d4.x], 1);
    atomicAdd(&g_cnt[bo + d4.y], 1);
    atomicAdd(&g_cnt[bo + d4.z], 1);
    atomicAdd(&g_cnt[bo + d4.w], 1);
}

// ---------------- single-pass decoupled-lookback scan ----------------
__global__ __launch_bounds__(256) void scan_kernel()
{
    __shared__ int sm[256];
    __shared__ int s_prefix;

    const int tile  = blockIdx.x;
    const int tid   = threadIdx.x;
    const int tbase = tile * 1024;

    int4 v = *(const int4*)(g_cnt + tbase + tid * 4);
    int tsum = v.x + v.y + v.z + v.w;

    sm[tid] = tsum;
    __syncthreads();
    for (int ofs = 1; ofs < 256; ofs <<= 1) {
        int t = (tid >= ofs) ? sm[tid - ofs] : 0;
        __syncthreads();
        sm[tid] += t;
        __syncthreads();
    }
    int excl  = sm[tid] - tsum;
    int total = sm[255];

    if (tid == 0) {
        if (tile == 0) {
            atomicExch(&g_state[0], (2ULL << 32) | (unsigned)total);
            s_prefix = 0;
        } else {
            atomicExch(&g_state[tile], (1ULL << 32) | (unsigned)total);
            long long run = 0;
            int t = tile - 1;
            while (true) {
                unsigned long long st;
                do { st = atomicAdd(&g_state[t], 0ULL); } while ((st >> 32) == 0);
                run += (unsigned)st;
                if ((st >> 32) == 2) break;
                t--;
            }
            atomicExch(&g_state[tile], (2ULL << 32) | (unsigned)(run + total));
            s_prefix = (int)run;
        }
    }
    __syncthreads();

    int base = s_prefix + excl;
    int4 o;
    o.x = base;
    o.y = o.x + v.x;
    o.z = o.y + v.y;
    o.w = o.z + v.z;
    *(int4*)(g_off + tbase + tid * 4) = o;
    *(int4*)(g_cur + tbase + tid * 4) = o;
}

// ---------------- Phase B+C fused: HALF-WARP per row, 16B lanes, fp16 accum, MLP=2 ----
// 8 warps/CTA, 2 rows per warp (one per 16-lane half) -> 16 rows per CTA
__global__ __launch_bounds__(256) void agg_combine(
    float* __restrict__ out, const int* __restrict__ merge)
{
    const int lane = threadIdx.x & 31;
    const int sub  = lane & 15;                     // uint4 index within 256B row
    const int r = blockIdx.x * 16 + ((threadIdx.x >> 5) << 1) + (lane >> 4);

    int blk = 0;
#pragma unroll
    for (int k = 1; k < 16; k++)
        if (r >= c_blkoff[k]) blk = k;
    const int s = blk >> 2, d = blk & 3;
    const int lrow = r - c_blkoff[blk];

    const int base = g_off[r];
    const int deg  = g_cnt[r];
    const uint4* FNs = (const uint4*)(g_FN + (size_t)s * NN * OO);   // 16 uint4 per row

    __half2 hz; *(unsigned*)&hz = 0u;
    __half2 ha0 = hz, ha1 = hz, ha2 = hz, ha3 = hz;
    __half2 hb0 = hz, hb1 = hz, hb2 = hz, hb3 = hz;

    for (int i0 = 0; i0 < deg; i0 += 16) {
        int mi = i0 + sub;
        int msrc = (mi < deg) ? (int)g_sorted_src[base + mi] : 0;
        int cnt = min(16, deg - i0);
        int fullc = cnt & ~1;
        int j = 0;
        for (; j < fullc; j += 2) {
            int s0 = __shfl_sync(0xffffffffu, msrc, j, 16);
            int s1 = __shfl_sync(0xffffffffu, msrc, j + 1, 16);
            uint4 ra = __ldg(FNs + (size_t)s0 * 16 + sub);
            uint4 rb = __ldg(FNs + (size_t)s1 * 16 + sub);
            ha0 = __hadd2(ha0, *(__half2*)&ra.x);
            ha1 = __hadd2(ha1, *(__half2*)&ra.y);
            ha2 = __hadd2(ha2, *(__half2*)&ra.z);
            ha3 = __hadd2(ha3, *(__half2*)&ra.w);
            hb0 = __hadd2(hb0, *(__half2*)&rb.x);
            hb1 = __hadd2(hb1, *(__half2*)&rb.y);
            hb2 = __hadd2(hb2, *(__half2*)&rb.z);
            hb3 = __hadd2(hb3, *(__half2*)&rb.w);
        }
        if (j < cnt) {
            int s0 = __shfl_sync(0xffffffffu, msrc, j, 16);
            uint4 ra = __ldg(FNs + (size_t)s0 * 16 + sub);
            ha0 = __hadd2(ha0, *(__half2*)&ra.x);
            ha1 = __hadd2(ha1, *(__half2*)&ra.y);
            ha2 = __hadd2(ha2, *(__half2*)&ra.z);
            ha3 = __hadd2(ha3, *(__half2*)&ra.w);
        }
    }
    ha0 = __hadd2(ha0, hb0);
    ha1 = __hadd2(ha1, hb1);
    ha2 = __hadd2(ha2, hb2);
    ha3 = __hadd2(ha3, hb3);

    float2 f0 = __half22float2(ha0);
    float2 f1 = __half22float2(ha1);
    float2 f2 = __half22float2(ha2);
    float2 f3 = __half22float2(ha3);

    const float invd = (deg > 0) ? (1.0f / (float)deg) : 0.0f;
    const int c0 = sub * 8;     // 8 output cols per lane

    if (s == d) {
        if (deg == 0) return;
        float* op = out + ((size_t)d * NN + lrow) * OO + c0;
        asm volatile("red.global.add.v4.f32 [%0], {%1,%2,%3,%4};"
                     :: "l"(op),
                        "f"(f0.x * invd), "f"(f0.y * invd),
                        "f"(f1.x * invd), "f"(f1.y * invd) : "memory");
        asm volatile("red.global.add.v4.f32 [%0], {%1,%2,%3,%4};"
                     :: "l"(op + 4),
                        "f"(f2.x * invd), "f"(f2.y * invd),
                        "f"(f3.x * invd), "f"(f3.y * invd) : "memory");
    } else {
        uint4 smr = *(const uint4*)(g_SelfM + ((size_t)s * MM + lrow) * OO + c0);
        float2 s0 = __half22float2(*(__half2*)&smr.x);
        float2 s1 = __half22float2(*(__half2*)&smr.y);
        float2 s2 = __half22float2(*(__half2*)&smr.z);
        float2 s3 = __half22float2(*(__half2*)&smr.w);
        int tgt = __ldg(merge + (size_t)blk * MM + lrow);
        float* op = out + ((size_t)d * NN + tgt) * OO + c0;
        asm volatile("red.global.add.v4.f32 [%0], {%1,%2,%3,%4};"
                     :: "l"(op),
                        "f"(fmaf(f0.x, invd, s0.x)), "f"(fmaf(f0.y, invd, s0.y)),
                        "f"(fmaf(f1.x, invd, s1.x)), "f"(fmaf(f1.y, invd, s1.y)) : "memory");
        asm volatile("red.global.add.v4.f32 [%0], {%1,%2,%3,%4};"
                     :: "l"(op + 4),
                        "f"(fmaf(f2.x, invd, s2.x)), "f"(fmaf(f2.y, invd, s2.y)),
                        "f"(fmaf(f3.x, invd, s3.x)), "f"(fmaf(f3.y, invd, s3.y)) : "memory");
    }
}

// ---------------- launch ----------------
extern "C" void kernel_launch(void* const* d_in, const int* in_sizes, int n_in,
                              void* d_out, int out_size)
{
    const float* feats  = (const float*)d_in[0];   // [P,N,D]
    const float* Wself  = (const float*)d_in[1];   // [P,D,O]
    const float* Wneigh = (const float*)d_in[2];   // [P,D,O]
    const float* bias   = (const float*)d_in[3];   // [P,O]
    const int*   e_src  = (const int*)d_in[4];     // [P,P,E]
    const int*   e_dst  = (const int*)d_in[5];     // [P,P,E]
    const int*   merge  = (const int*)d_in[6];     // [P,P,M]
    float* out = (float*)d_out;                    // [P,N,O]

    void* cntPtr = nullptr; cudaGetSymbolAddress(&cntPtr, g_cnt);
    void* stPtr  = nullptr; cudaGetSymbolAddress(&stPtr,  g_state);
    cudaMemsetAsync(cntPtr, 0, sizeof(int) * (size_t)TOTAL_ROWS, 0);
    cudaMemsetAsync(stPtr,  0, sizeof(unsigned long long) * NTILES, 0);

    hist_kernel<<<(NEDGES / 4 + 255) / 256, 256>>>(e_dst);
    scan_kernel<<<NTILES, 256>>>();

    gemm_scatter<<<F2_GRID, 256>>>(feats, Wself, Wneigh, bias, out, e_src, e_dst);

    agg_combine<<<TOTAL_ROWS / 16, 256>>>(out, merge);
}